// round 5
// baseline (speedup 1.0000x reference)
#include <cuda_runtime.h>
#include <math.h>

#define SS 1024
#define HH 768
#define KK 32
#define MM 8
#define GG 32
#define VN 32000
#define JT 128

// ---------------- device scratch (static, no runtime alloc) ----------------
__device__ float g_base[SS*HH];
__device__ float g_fpraw[SS*KK*2];
__device__ float g_impraw[SS*KK];
__device__ float g_a1[SS*KK];
__device__ float g_b1[SS*KK];
__device__ float g_lnrm[SS*KK];
__device__ double g_a1d[SS*KK];
__device__ double g_b1d[SS*KK];
__device__ double g_lnd[SS*KK];
__device__ float g_imp[SS*KK];
__device__ float g_Lx[SS];
__device__ float g_L1[SS];
__device__ float g_chunk[SS*KK*HH];
__device__ float g_cmean[SS*HH];
__device__ float g_jsp[SS];
__device__ int   g_top[SS*MM];
__device__ float g_sel[SS*MM*HH];
__device__ float g_q[SS*HH];
__device__ float g_kbuf[SS*MM*HH];
__device__ float g_vbuf[SS*MM*HH];
__device__ float g_ft[SS*HH];
__device__ float g_gate[SS];
__device__ float g_hid[SS*HH];

// 32-point Gauss-Legendre on [0,1] (nodes (x+1)/2, weights w/2), order irrelevant.
__constant__ float c_node[32] = {
    0.5f*(1.0f-0.0483076656877383162f), 0.5f*(1.0f-0.1444719615827964934f),
    0.5f*(1.0f-0.2392873622521370745f), 0.5f*(1.0f-0.3318686022821276498f),
    0.5f*(1.0f-0.4213512761306353453f), 0.5f*(1.0f-0.5068999089322293900f),
    0.5f*(1.0f-0.5877157572407623290f), 0.5f*(1.0f-0.6630442669302152009f),
    0.5f*(1.0f-0.7321821187402896804f), 0.5f*(1.0f-0.7944837959679424069f),
    0.5f*(1.0f-0.8493676137325699701f), 0.5f*(1.0f-0.8963211557660521240f),
    0.5f*(1.0f-0.9349060759377396892f), 0.5f*(1.0f-0.9647622555875064308f),
    0.5f*(1.0f-0.9856115115452683354f), 0.5f*(1.0f-0.9972638618494815635f),
    0.5f*(1.0f+0.0483076656877383162f), 0.5f*(1.0f+0.1444719615827964934f),
    0.5f*(1.0f+0.2392873622521370745f), 0.5f*(1.0f+0.3318686022821276498f),
    0.5f*(1.0f+0.4213512761306353453f), 0.5f*(1.0f+0.5068999089322293900f),
    0.5f*(1.0f+0.5877157572407623290f), 0.5f*(1.0f+0.6630442669302152009f),
    0.5f*(1.0f+0.7321821187402896804f), 0.5f*(1.0f+0.7944837959679424069f),
    0.5f*(1.0f+0.8493676137325699701f), 0.5f*(1.0f+0.8963211557660521240f),
    0.5f*(1.0f+0.9349060759377396892f), 0.5f*(1.0f+0.9647622555875064308f),
    0.5f*(1.0f+0.9856115115452683354f), 0.5f*(1.0f+0.9972638618494815635f)
};
// weights: indices 13,14 corrected (0.02539206530926206, 0.01627439473090567);
// halves now sum to exactly 1.
__constant__ float c_gw[32] = {
    0.5f*0.0965400885147278006f, 0.5f*0.0956387200792748594f,
    0.5f*0.0938443990808045654f, 0.5f*0.0911738786957638847f,
    0.5f*0.0876520930044038111f, 0.5f*0.0833119242269467552f,
    0.5f*0.0781938957870703065f, 0.5f*0.0723457941088485062f,
    0.5f*0.0658222227763618468f, 0.5f*0.0586840934785355471f,
    0.5f*0.0509980592623761762f, 0.5f*0.0428358980222266807f,
    0.5f*0.0342738629130214331f, 0.5f*0.0253920653092620595f,
    0.5f*0.0162743947309056706f, 0.5f*0.0070186100094700966f,
    0.5f*0.0965400885147278006f, 0.5f*0.0956387200792748594f,
    0.5f*0.0938443990808045654f, 0.5f*0.0911738786957638847f,
    0.5f*0.0876520930044038111f, 0.5f*0.0833119242269467552f,
    0.5f*0.0781938957870703065f, 0.5f*0.0723457941088485062f,
    0.5f*0.0658222227763618468f, 0.5f*0.0586840934785355471f,
    0.5f*0.0509980592623761762f, 0.5f*0.0428358980222266807f,
    0.5f*0.0342738629130214331f, 0.5f*0.0253920653092620595f,
    0.5f*0.0162743947309056706f, 0.5f*0.0070186100094700966f
};

__device__ __forceinline__ float softplusf(float x) {
    return fmaxf(x, 0.0f) + log1pf(expf(-fabsf(x)));
}
__device__ __forceinline__ double softplusd(double x) {
    return fmax(x, 0.0) + log1p(exp(-fabs(x)));
}

// ---------------------------------------------------------------------------
__global__ void gather_base_kernel(const int* __restrict__ ids,
                                   const float* __restrict__ emb) {
    int t = blockIdx.x;
    int h = threadIdx.x;
    int id = ids[t];
    g_base[t*HH + h] = emb[(long)id*HH + h];
}

__global__ void logs_kernel() {
    int j = blockIdx.x*blockDim.x + threadIdx.x;
    if (j < SS) {
        float x = ((float)j + 0.5f) * (1.0f/(float)SS);
        x = fminf(fmaxf(x, 1e-5f), 1.0f - 1e-5f);
        g_Lx[j] = logf(x);
        g_L1[j] = log1pf(-x);
    }
}

// ------------------------ generic SGEMM: C = A @ B^T + bias ----------------
#define BM 64
#define BN 64
#define BK 16
__global__ __launch_bounds__(256) void sgemm_bias(
    const float* __restrict__ A, const float* __restrict__ B,
    const float* __restrict__ bias, float* __restrict__ C,
    int Mr, int Nr, int Kr)
{
    __shared__ float As[BK][BM+4];
    __shared__ float Bs[BK][BN+4];
    int tx = threadIdx.x & 15;
    int ty = threadIdx.x >> 4;
    int row0 = blockIdx.y*BM;
    int col0 = blockIdx.x*BN;
    float acc[4][4];
    #pragma unroll
    for (int i = 0; i < 4; i++)
        #pragma unroll
        for (int j = 0; j < 4; j++) acc[i][j] = 0.f;

    for (int k0 = 0; k0 < Kr; k0 += BK) {
        #pragma unroll
        for (int l = 0; l < 4; l++) {
            int lin = threadIdx.x + l*256;
            int r = lin >> 4, c = lin & 15;
            int gr = row0 + r;
            As[c][r] = (gr < Mr) ? A[(long)gr*Kr + k0 + c] : 0.f;
        }
        #pragma unroll
        for (int l = 0; l < 4; l++) {
            int lin = threadIdx.x + l*256;
            int r = lin >> 4, c = lin & 15;
            int gc = col0 + r;
            Bs[c][r] = (gc < Nr) ? B[(long)gc*Kr + k0 + c] : 0.f;
        }
        __syncthreads();
        #pragma unroll
        for (int c = 0; c < BK; c++) {
            float4 a4 = *(const float4*)&As[c][ty*4];
            float4 b4 = *(const float4*)&Bs[c][tx*4];
            float ar[4] = {a4.x, a4.y, a4.z, a4.w};
            float br[4] = {b4.x, b4.y, b4.z, b4.w};
            #pragma unroll
            for (int i = 0; i < 4; i++)
                #pragma unroll
                for (int j = 0; j < 4; j++)
                    acc[i][j] = fmaf(ar[i], br[j], acc[i][j]);
        }
        __syncthreads();
    }
    #pragma unroll
    for (int i = 0; i < 4; i++) {
        int gr = row0 + ty*4 + i;
        if (gr >= Mr) continue;
        #pragma unroll
        for (int j = 0; j < 4; j++) {
            int gc = col0 + tx*4 + j;
            if (gc >= Nr) continue;
            float v = acc[i][j];
            if (bias) v += bias[gc];
            C[(long)gr*Nr + gc] = v;
        }
    }
}

// ------------------------ params (shift + softplus + lgamma) ----------------
__global__ void params_kernel() {
    int t = blockIdx.x, k = threadIdx.x;
    float fa = 0.f, fb = 0.f, im = 0.f;
    if (t > 0) {
        fa = g_fpraw[(t-1)*(KK*2) + k*2 + 0];
        fb = g_fpraw[(t-1)*(KK*2) + k*2 + 1];
        im = softplusf(g_impraw[(t-1)*KK + k]);
    }
    double al = softplusd((double)fa) + 1e-4;
    double be = softplusd((double)fb) + 1e-4;
    double ln = lgamma(al) + lgamma(be) - lgamma(al + be);
    g_a1d[t*KK+k] = al - 1.0;
    g_b1d[t*KK+k] = be - 1.0;
    g_lnd[t*KK+k] = ln;
    g_a1[t*KK+k] = (float)(al - 1.0);
    g_b1[t*KK+k] = (float)(be - 1.0);
    g_lnrm[t*KK+k] = (float)ln;
    g_imp[t*KK+k] = im;
}

// ------------------- fused pdf + normalize + chunk einsum -------------------
__global__ __launch_bounds__(768, 1) void chunk_kernel() {
    int t = blockIdx.x;
    int tid = threadIdx.x;
    __shared__ float a1s[KK], b1s[KK], lns[KK], sca[KK], Zs[KK];
    __shared__ float buf[2][JT*KK];

    if (tid < KK) {
        a1s[tid] = g_a1[t*KK+tid];
        b1s[tid] = g_b1[t*KK+tid];
        lns[tid] = g_lnrm[t*KK+tid];
        Zs[tid] = 0.f;
    }
    __syncthreads();

    float acc[KK];
    #pragma unroll
    for (int k = 0; k < KK; k++) acc[k] = 0.f;

    int ntiles = (t + JT) / JT;   // ceil((t+1)/JT)

    // produce tile 0
    for (int v = tid; v < JT*KK; v += 768) {
        int jl = v >> 5, k = v & 31;
        int j = jl;
        float e = 0.f;
        if (j <= t)
            e = __expf(fmaf(a1s[k], g_Lx[j], fmaf(b1s[k], g_L1[j], -lns[k])));
        buf[0][v] = e;
    }
    __syncthreads();

    for (int tile = 0; tile < ntiles; tile++) {
        int p = tile & 1;
        if (tile + 1 < ntiles) {
            int jb = (tile+1)*JT;
            for (int v = tid; v < JT*KK; v += 768) {
                int jl = v >> 5, k = v & 31;
                int j = jb + jl;
                float e = 0.f;
                if (j <= t)
                    e = __expf(fmaf(a1s[k], g_Lx[j], fmaf(b1s[k], g_L1[j], -lns[k])));
                buf[1-p][v] = e;
            }
        }
        int jb = tile*JT;
        int jend = min(jb + JT - 1, t);
        float zpart = 0.f;
        #pragma unroll 4
        for (int j = jb; j <= jend; j++) {
            float b = g_base[j*HH + tid];
            const float4* w4 = (const float4*)&buf[p][(j - jb)*KK];
            #pragma unroll
            for (int q = 0; q < 8; q++) {
                float4 w = w4[q];
                acc[q*4+0] = fmaf(w.x, b, acc[q*4+0]);
                acc[q*4+1] = fmaf(w.y, b, acc[q*4+1]);
                acc[q*4+2] = fmaf(w.z, b, acc[q*4+2]);
                acc[q*4+3] = fmaf(w.w, b, acc[q*4+3]);
            }
            if (tid < KK) zpart += buf[p][(j - jb)*KK + tid];
        }
        if (tid < KK) Zs[tid] += zpart;
        __syncthreads();
    }

    if (tid < KK) sca[tid] = g_imp[t*KK+tid] / (Zs[tid] + 1e-9f);
    __syncthreads();

    float cm = 0.f;
    #pragma unroll
    for (int k = 0; k < KK; k++) {
        float v = acc[k] * sca[k];
        g_chunk[((long)t*KK + k)*HH + tid] = v;
        cm += v;
    }
    g_cmean[t*HH + tid] = cm * (1.0f/(float)KK);
}

// ------------------------------- JS divergence -------------------------------
__global__ __launch_bounds__(512) void js_kernel() {
    int t = blockIdx.x;
    int tid = threadIdx.x;
    __shared__ double pd[KK*GG];
    __shared__ double a1s[KK], b1s[KK], lns[KK];
    __shared__ double lgx[GG], lg1[GG];
    __shared__ float gws[GG];
    __shared__ float red[16];

    if (tid < KK) {
        a1s[tid] = g_a1d[t*KK+tid];
        b1s[tid] = g_b1d[t*KK+tid];
        lns[tid] = g_lnd[t*KK+tid];
        double nd = (double)c_node[tid];
        nd = fmin(fmax(nd, 1e-5), 1.0 - 1e-5);
        lgx[tid] = log(nd);
        lg1[tid] = log1p(-nd);
        gws[tid] = c_gw[tid];
    }
    __syncthreads();
    for (int v = tid; v < KK*GG; v += 512) {
        int k = v >> 5, g = v & 31;
        pd[v] = exp(a1s[k]*lgx[g] + b1s[k]*lg1[g] - lns[k]);
    }
    __syncthreads();

    float sum = 0.f;
    if (tid < 496) {
        int idx = tid, i = 0, rem = 31;
        while (idx >= rem) { idx -= rem; i++; rem--; }
        int j = i + 1 + idx;
        #pragma unroll
        for (int g = 0; g < GG; g++) {
            double pi = pd[i*GG+g], pj = pd[j*GG+g];
            double me = 0.5*(pi+pj) + 1e-9;
            double dd = 0.5*(pi-pj);
            float inv = 1.0f/(float)me;
            float r = (float)dd * inv;
            float term = (float)pi * log1pf(r) + (float)pj * log1pf(-r);
            sum += gws[g]*0.5f*term;
        }
    }
    #pragma unroll
    for (int o = 16; o; o >>= 1) sum += __shfl_xor_sync(0xffffffffu, sum, o);
    int w = tid >> 5, lane = tid & 31;
    if (lane == 0) red[w] = sum;
    __syncthreads();
    if (tid == 0) {
        float s = 0.f;
        for (int i = 0; i < 16; i++) s += red[i];
        g_jsp[t] = s;
    }
}

__global__ void jsred_kernel(float* out, int out_size) {
    __shared__ double sm[SS];
    int tid = threadIdx.x;
    sm[tid] = (double)g_jsp[tid];
    __syncthreads();
    for (int s = SS/2; s; s >>= 1) {
        if (tid < s) sm[tid] += sm[tid+s];
        __syncthreads();
    }
    if (tid == 0) out[out_size-1] = (float)(sm[0] / 507904.0);
}

// --------------------------------- top-k -------------------------------------
__global__ void topk_kernel() {
    int t = blockIdx.x, lane = threadIdx.x;
    float v = g_imp[t*KK + lane];
    for (int m = 0; m < MM; m++) {
        float bv = v; int bi = lane;
        #pragma unroll
        for (int o = 16; o; o >>= 1) {
            float ov = __shfl_xor_sync(0xffffffffu, bv, o);
            int oi = __shfl_xor_sync(0xffffffffu, bi, o);
            if (ov > bv || (ov == bv && oi < bi)) { bv = ov; bi = oi; }
        }
        if (lane == 0) g_top[t*MM + m] = bi;
        if (lane == bi) v = -__int_as_float(0x7f800000);
    }
}

__global__ void selgather_kernel() {
    int blk = blockIdx.x;          // t*MM + m
    int t = blk >> 3;
    int idx = g_top[blk];
    g_sel[(long)blk*HH + threadIdx.x] = g_chunk[((long)t*KK + idx)*HH + threadIdx.x];
}

// ------------------------------- attention -----------------------------------
__global__ __launch_bounds__(256) void attn_kernel() {
    int t = blockIdx.x, tid = threadIdx.x;
    int w = tid >> 5, lane = tid & 31;
    __shared__ float sc[MM], at[MM];
    float s = 0.f;
    for (int h = lane; h < HH; h += 32)
        s += g_q[t*HH + h] * g_kbuf[((long)t*MM + w)*HH + h];
    #pragma unroll
    for (int o = 16; o; o >>= 1) s += __shfl_xor_sync(0xffffffffu, s, o);
    if (lane == 0) sc[w] = s * (1.0f/27.712812921102035f);  // 1/sqrt(768)
    __syncthreads();
    if (tid == 0) {
        float mx = sc[0];
        for (int m = 1; m < MM; m++) mx = fmaxf(mx, sc[m]);
        float ssum = 0.f;
        for (int m = 0; m < MM; m++) { float e = expf(sc[m]-mx); at[m] = e; ssum += e; }
        float inv = 1.0f/ssum;
        for (int m = 0; m < MM; m++) at[m] *= inv;
    }
    __syncthreads();
    for (int h = tid; h < HH; h += 256) {
        float f = 0.f;
        #pragma unroll
        for (int m = 0; m < MM; m++)
            f += at[m] * g_vbuf[((long)t*MM + m)*HH + h];
        g_ft[t*HH + h] = f;
    }
}

// --------------------------------- gate --------------------------------------
__global__ __launch_bounds__(256) void gate_kernel(const float* __restrict__ hpen,
                                                   const float* __restrict__ gw,
                                                   const float* __restrict__ gb) {
    int t = blockIdx.x, tid = threadIdx.x;
    __shared__ float red[8];
    float s = 0.f;
    for (int h = tid; h < HH; h += 256)
        s += hpen[t*HH+h]*gw[h] + g_cmean[t*HH+h]*gw[HH+h];
    #pragma unroll
    for (int o = 16; o; o >>= 1) s += __shfl_xor_sync(0xffffffffu, s, o);
    int w = tid >> 5, lane = tid & 31;
    if (lane == 0) red[w] = s;
    __syncthreads();
    if (tid == 0) {
        float tot = 0.f;
        for (int i = 0; i < 8; i++) tot += red[i];
        g_gate[t] = 1.0f/(1.0f + expf(-(tot + gb[0])));
    }
}

// ------------------------------ gated + LN ------------------------------------
__global__ __launch_bounds__(256) void ln_kernel(const float* __restrict__ hfin,
                                                 const float* __restrict__ lng,
                                                 const float* __restrict__ lnb) {
    int t = blockIdx.x, tid = threadIdx.x;
    __shared__ float hb[HH];
    __shared__ float red[8];
    __shared__ float s_mean, s_var;
    float gt = g_gate[t];
    float s = 0.f;
    for (int h = tid; h < HH; h += 256) {
        float hv = gt*g_ft[t*HH+h] + (1.0f-gt)*hfin[t*HH+h];
        hb[h] = hv;
        s += hv;
    }
    #pragma unroll
    for (int o = 16; o; o >>= 1) s += __shfl_xor_sync(0xffffffffu, s, o);
    int w = tid >> 5, lane = tid & 31;
    if (lane == 0) red[w] = s;
    __syncthreads();
    if (tid == 0) {
        float tot = 0.f;
        for (int i = 0; i < 8; i++) tot += red[i];
        s_mean = tot * (1.0f/(float)HH);
    }
    __syncthreads();
    float mean = s_mean;
    float v = 0.f;
    for (int h = tid; h < HH; h += 256) {
        float d = hb[h] - mean;
        v += d*d;
    }
    #pragma unroll
    for (int o = 16; o; o >>= 1) v += __shfl_xor_sync(0xffffffffu, v, o);
    if (lane == 0) red[w] = v;
    __syncthreads();
    if (tid == 0) {
        float tot = 0.f;
        for (int i = 0; i < 8; i++) tot += red[i];
        s_var = tot * (1.0f/(float)HH);
    }
    __syncthreads();
    float inv = rsqrtf(s_var + 1e-5f);
    for (int h = tid; h < HH; h += 256)
        g_hid[t*HH+h] = (hb[h]-mean)*inv*lng[h] + lnb[h];
}

// ------------------------------------------------------------------------------
extern "C" void kernel_launch(void* const* d_in, const int* in_sizes, int n_in,
                              void* d_out, int out_size) {
    const int*   ids     = (const int*)  d_in[0];
    const float* emb     = (const float*)d_in[1];
    const float* h_pen   = (const float*)d_in[2];
    const float* h_final = (const float*)d_in[3];
    const float* focus_w = (const float*)d_in[4];
    const float* focus_b = (const float*)d_in[5];
    const float* imp_w   = (const float*)d_in[6];
    const float* imp_b   = (const float*)d_in[7];
    const float* q_w     = (const float*)d_in[8];
    const float* q_b     = (const float*)d_in[9];
    const float* k_w     = (const float*)d_in[10];
    const float* k_b     = (const float*)d_in[11];
    const float* v_w     = (const float*)d_in[12];
    const float* v_b     = (const float*)d_in[13];
    const float* gate_w  = (const float*)d_in[14];
    const float* gate_b  = (const float*)d_in[15];
    const float* ln_g    = (const float*)d_in[16];
    const float* ln_b    = (const float*)d_in[17];
    const float* lm_w    = (const float*)d_in[18];
    float* out = (float*)d_out;

    float* p_fpraw; cudaGetSymbolAddress((void**)&p_fpraw, g_fpraw);
    float* p_impr;  cudaGetSymbolAddress((void**)&p_impr,  g_impraw);
    float* p_sel;   cudaGetSymbolAddress((void**)&p_sel,   g_sel);
    float* p_q;     cudaGetSymbolAddress((void**)&p_q,     g_q);
    float* p_k;     cudaGetSymbolAddress((void**)&p_k,     g_kbuf);
    float* p_v;     cudaGetSymbolAddress((void**)&p_v,     g_vbuf);
    float* p_hid;   cudaGetSymbolAddress((void**)&p_hid,   g_hid);

    gather_base_kernel<<<SS, HH>>>(ids, emb);
    logs_kernel<<<2, 512>>>();

    sgemm_bias<<<dim3(1,16), 256>>>(h_pen, focus_w, focus_b, p_fpraw, SS, KK*2, HH);
    sgemm_bias<<<dim3(1,16), 256>>>(h_pen, imp_w,   imp_b,   p_impr,  SS, KK,   HH);
    params_kernel<<<SS, KK>>>();

    chunk_kernel<<<SS, HH>>>();

    js_kernel<<<SS, 512>>>();
    jsred_kernel<<<1, SS>>>(out, out_size);

    topk_kernel<<<SS, 32>>>();
    selgather_kernel<<<SS*MM, HH>>>();

    sgemm_bias<<<dim3(HH/BN, SS/BM),    256>>>(h_final, q_w, q_b, p_q, SS,    HH, HH);
    sgemm_bias<<<dim3(HH/BN, SS*MM/BM), 256>>>(p_sel,   k_w, k_b, p_k, SS*MM, HH, HH);
    sgemm_bias<<<dim3(HH/BN, SS*MM/BM), 256>>>(p_sel,   v_w, v_b, p_v, SS*MM, HH, HH);

    attn_kernel<<<SS, 256>>>();
    gate_kernel<<<SS, 256>>>(h_pen, gate_w, gate_b);
    ln_kernel<<<SS, 256>>>(h_final, ln_g, ln_b);

    sgemm_bias<<<dim3(VN/BN, SS/BM), 256>>>(p_hid, lm_w, (const float*)nullptr, out, SS, VN, HH);
}